// round 14
// baseline (speedup 1.0000x reference)
#include <cuda_runtime.h>
#include <cuda_fp16.h>
#include <cuda_bf16.h>

// Pairwise max-margin hinge loss — SINGLE graph node.
// 1056 blocks = 528 unordered 32x32 tile-pairs x 2 batch-halves; 256 thr.
// fp16 batch-pair packing: half2 lanes = (batch b0, batch b1); HFMA2.RELU.
// Finalize: per-block RED into g_acc + release-atom counter; last block
// acquires, writes d_out, resets globals (replay-deterministic, no memset).
// loss = [2*offdiag + diag] / (N*2).
// Inputs: out [N,B] f32, label [N,B] f32, margin [1] f32.  N=1024, B=32.

#define PN 1024
#define PB 32
#define NBLK (528 * 2)
#define THREADS 256
#define BH 16              // batches per block (8 pairs)
#define JS2 33             // J stride in half2 units
#define KS2 36             // K stride in half2 units (144B rows, 16B-aligned)

__device__ float    g_acc = 0.0f;   // cross-block accumulator
__device__ unsigned g_cnt = 0u;     // blocks-done counter

__global__ __launch_bounds__(THREADS)
void hinge_tile_kernel(const float* __restrict__ g_out,
                       const float* __restrict__ g_label,
                       const float* __restrict__ g_margin,
                       float* __restrict__ result)
{
    // Layout: [batch-pair][n] of half2 {b0, b1}.
    __shared__ __half s_oJ[(BH / 2) * JS2 * 2];
    __shared__ __half s_lJ[(BH / 2) * JS2 * 2];
    __shared__ alignas(16) __half s_oK[(BH / 2) * KS2 * 2];
    __shared__ alignas(16) __half s_lK[(BH / 2) * KS2 * 2];
    __shared__ float warp_sums[THREADS / 32];

    const int p = blockIdx.x >> 1;      // 0..527: unordered tile pair
    const int h = blockIdx.x & 1;       // batch half

    int jt, kt;
    float w;
    if (p < 480)      { int dt = (p >> 5) + 1; jt = p & 31; kt = (jt + dt) & 31; w = 2.0f; }
    else if (p < 496) { jt = p - 480; kt = jt + 16; w = 2.0f; }
    else              { jt = p - 496; kt = jt;      w = 1.0f; }

    const int t    = threadIdx.x;
    const int wid  = t >> 5;
    const int lane = t & 31;

    // Stage with float4 LDG: 128 float4 per array; threads 0-127 do the J
    // arrays, 128-255 the K arrays (o and l each). Two LDG.128 per thread.
    {
        const int i  = t & 127;         // float4 index within array
        const int n  = i >> 2;          // tile row 0..31
        const int bl = (i & 3) * 4;     // first of 4 consecutive batches
        const int go = n * PB + bl;     // element offset within (tile, half)
        const int bp = bl >> 1;         // first batch-pair index

        if (t < 128) {
            const float4 o4 = *(const float4*)(g_out   + jt * 1024 + h * BH + go);
            const float4 l4 = *(const float4*)(g_label + jt * 1024 + h * BH + go);
            __half2* dsto = (__half2*)s_oJ;
            __half2* dstl = (__half2*)s_lJ;
            dsto[(bp + 0) * JS2 + n] = __floats2half2_rn(o4.x, o4.y);
            dsto[(bp + 1) * JS2 + n] = __floats2half2_rn(o4.z, o4.w);
            dstl[(bp + 0) * JS2 + n] = __floats2half2_rn(l4.x, l4.y);
            dstl[(bp + 1) * JS2 + n] = __floats2half2_rn(l4.z, l4.w);
        } else {
            const float4 o4 = *(const float4*)(g_out   + kt * 1024 + h * BH + go);
            const float4 l4 = *(const float4*)(g_label + kt * 1024 + h * BH + go);
            __half2* dsto = (__half2*)s_oK;
            __half2* dstl = (__half2*)s_lK;
            dsto[(bp + 0) * KS2 + n] = __floats2half2_rn(o4.x, o4.y);
            dsto[(bp + 1) * KS2 + n] = __floats2half2_rn(o4.z, o4.w);
            dstl[(bp + 0) * KS2 + n] = __floats2half2_rn(l4.x, l4.y);
            dstl[(bp + 1) * KS2 + n] = __floats2half2_rn(l4.z, l4.w);
        }
    }
    __syncthreads();

    const __half2 m2 = __float2half2_rn(g_margin[0]);

    // Warp wid owns batch-pair wid; lane = j row in the J tile.
    const __half2 oj2 = ((const __half2*)s_oJ)[wid * JS2 + lane];
    const __half2 lj2 = ((const __half2*)s_lJ)[wid * JS2 + lane];
    const uint4* ko = (const uint4*)(s_oK + wid * KS2 * 2);   // 4 k per uint4
    const uint4* kl = (const uint4*)(s_lK + wid * KS2 * 2);

    __half2 a0 = __float2half2_rn(0.f), a1 = a0, a2 = a0, a3 = a0;

    #pragma unroll
    for (int g = 0; g < 8; g++) {       // 4 k per group, 32 k total
        uint4 o4 = ko[g];               // LDS.128, warp-uniform broadcast
        uint4 l4 = kl[g];
        const __half2 ox = *(const __half2*)&o4.x, oy = *(const __half2*)&o4.y;
        const __half2 oz = *(const __half2*)&o4.z, ow = *(const __half2*)&o4.w;
        const __half2 lx = *(const __half2*)&l4.x, ly = *(const __half2*)&l4.y;
        const __half2 lz = *(const __half2*)&l4.z, lw = *(const __half2*)&l4.w;

        // relu(m + (ok-oj)*(lj-lk)), both batches at once.
        a0 = __hadd2(a0, __hfma2_relu(__hsub2(ox, oj2), __hsub2(lj2, lx), m2));
        a1 = __hadd2(a1, __hfma2_relu(__hsub2(oy, oj2), __hsub2(lj2, ly), m2));
        a2 = __hadd2(a2, __hfma2_relu(__hsub2(oz, oj2), __hsub2(lj2, lz), m2));
        a3 = __hadd2(a3, __hfma2_relu(__hsub2(ow, oj2), __hsub2(lj2, lw), m2));
    }

    float2 f0 = __half22float2(a0);
    float2 f1 = __half22float2(a1);
    float2 f2 = __half22float2(a2);
    float2 f3 = __half22float2(a3);
    float acc = (((f0.x + f0.y) + (f1.x + f1.y))
               + ((f2.x + f2.y) + (f3.x + f3.y))) * w;

    // Warp reduce.
    #pragma unroll
    for (int off = 16; off > 0; off >>= 1)
        acc += __shfl_xor_sync(0xFFFFFFFFu, acc, off);
    if (lane == 0) warp_sums[wid] = acc;
    __syncthreads();

    // Cheap cross-block finalize: RED + release-atom counter (no MEMBAR.GPU).
    if (t == 0) {
        float s = 0.f;
        #pragma unroll
        for (int wdx = 0; wdx < THREADS / 32; wdx++) s += warp_sums[wdx];

        atomicAdd(&g_acc, s);           // REDG (result unused)

        unsigned old;
        asm volatile("atom.release.gpu.global.add.u32 %0, [%1], 1;"
                     : "=r"(old) : "l"(&g_cnt) : "memory");

        if (old == NBLK - 1) {          // last block: all REDs visible
            float total;
            asm volatile("ld.acquire.gpu.global.f32 %0, [%1];"
                         : "=f"(total) : "l"(&g_acc) : "memory");
            *result = total * (1.0f / (2.0f * PN));
            // Reset for the next graph replay (ordered by launch boundary).
            g_acc = 0.0f;
            g_cnt = 0u;
        }
    }
}

extern "C" void kernel_launch(void* const* d_in, const int* in_sizes, int n_in,
                              void* d_out, int out_size)
{
    const float* g_out    = (const float*)d_in[0];
    const float* g_label  = (const float*)d_in[1];
    const float* g_margin = (const float*)d_in[2];
    float*       result   = (float*)d_out;

    hinge_tile_kernel<<<NBLK, THREADS>>>(g_out, g_label, g_margin, result);
}

// round 15
// speedup vs baseline: 1.2357x; 1.2357x over previous
#include <cuda_runtime.h>
#include <cuda_fp16.h>
#include <cuda_bf16.h>

// Pairwise max-margin hinge loss — SINGLE graph node, no memset.
// 1056 blocks = 528 unordered 32x32 tile-pairs x 2 batch-halves; 256 thr.
// fp16 batch-pair packing: half2 lanes = (batch b0, batch b1); HFMA2.RELU.
// d_out zeroing: block 0 stores 0 as its FIRST action (wave-1 resident);
// every block's single atomicAdd lands only after ~5us of staging+compute,
// so the store strictly precedes all adds. One atomic round (R12-proven).
// loss = [2*offdiag + diag] / (N*2).
// Inputs: out [N,B] f32, label [N,B] f32, margin [1] f32.  N=1024, B=32.

#define PN 1024
#define PB 32
#define NBLK (528 * 2)
#define THREADS 256
#define BH 16              // batches per block (8 pairs)
#define JS2 33             // J stride in half2 units
#define KS2 36             // K stride in half2 units (144B rows, 16B-aligned)

__global__ __launch_bounds__(THREADS, 8)
void hinge_tile_kernel(const float* __restrict__ g_out,
                       const float* __restrict__ g_label,
                       const float* __restrict__ g_margin,
                       float* __restrict__ result)
{
    // Zero the output first thing, from the first-scheduled block.
    if (blockIdx.x == 0 && threadIdx.x == 0) {
        *result = 0.0f;
    }

    // Layout: [batch-pair][n] of half2 {b0, b1}.
    __shared__ __half s_oJ[(BH / 2) * JS2 * 2];
    __shared__ __half s_lJ[(BH / 2) * JS2 * 2];
    __shared__ alignas(16) __half s_oK[(BH / 2) * KS2 * 2];
    __shared__ alignas(16) __half s_lK[(BH / 2) * KS2 * 2];
    __shared__ float warp_sums[THREADS / 32];

    const int p = blockIdx.x >> 1;      // 0..527: unordered tile pair
    const int h = blockIdx.x & 1;       // batch half

    int jt, kt;
    float w;
    if (p < 480)      { int dt = (p >> 5) + 1; jt = p & 31; kt = (jt + dt) & 31; w = 2.0f; }
    else if (p < 496) { jt = p - 480; kt = jt + 16; w = 2.0f; }
    else              { jt = p - 496; kt = jt;      w = 1.0f; }

    const int t    = threadIdx.x;
    const int wid  = t >> 5;
    const int lane = t & 31;

    // Stage with float4 LDG: threads 0-127 stage the J tile, 128-255 the K
    // tile (o and l arrays each). Two LDG.128 + four half2 STS per thread.
    {
        const int i  = t & 127;         // float4 index within (tile, half)
        const int n  = i >> 2;          // tile row 0..31
        const int bl = (i & 3) * 4;     // first of 4 consecutive batches
        const int go = n * PB + bl;
        const int bp = bl >> 1;         // first batch-pair index

        if (t < 128) {
            const float4 o4 = *(const float4*)(g_out   + jt * 1024 + h * BH + go);
            const float4 l4 = *(const float4*)(g_label + jt * 1024 + h * BH + go);
            __half2* dsto = (__half2*)s_oJ;
            __half2* dstl = (__half2*)s_lJ;
            dsto[(bp + 0) * JS2 + n] = __floats2half2_rn(o4.x, o4.y);
            dsto[(bp + 1) * JS2 + n] = __floats2half2_rn(o4.z, o4.w);
            dstl[(bp + 0) * JS2 + n] = __floats2half2_rn(l4.x, l4.y);
            dstl[(bp + 1) * JS2 + n] = __floats2half2_rn(l4.z, l4.w);
        } else {
            const float4 o4 = *(const float4*)(g_out   + kt * 1024 + h * BH + go);
            const float4 l4 = *(const float4*)(g_label + kt * 1024 + h * BH + go);
            __half2* dsto = (__half2*)s_oK;
            __half2* dstl = (__half2*)s_lK;
            dsto[(bp + 0) * KS2 + n] = __floats2half2_rn(o4.x, o4.y);
            dsto[(bp + 1) * KS2 + n] = __floats2half2_rn(o4.z, o4.w);
            dstl[(bp + 0) * KS2 + n] = __floats2half2_rn(l4.x, l4.y);
            dstl[(bp + 1) * KS2 + n] = __floats2half2_rn(l4.z, l4.w);
        }
    }
    __syncthreads();

    const __half2 m2 = __float2half2_rn(g_margin[0]);

    // Warp wid owns batch-pair wid; lane = j row in the J tile.
    const __half2 oj2 = ((const __half2*)s_oJ)[wid * JS2 + lane];
    const __half2 lj2 = ((const __half2*)s_lJ)[wid * JS2 + lane];
    const uint4* ko = (const uint4*)(s_oK + wid * KS2 * 2);   // 4 k per uint4
    const uint4* kl = (const uint4*)(s_lK + wid * KS2 * 2);

    __half2 a0 = __float2half2_rn(0.f), a1 = a0, a2 = a0, a3 = a0;

    #pragma unroll
    for (int g = 0; g < 8; g++) {       // 4 k per group, 32 k total
        uint4 o4 = ko[g];               // LDS.128, warp-uniform broadcast
        uint4 l4 = kl[g];
        const __half2 ox = *(const __half2*)&o4.x, oy = *(const __half2*)&o4.y;
        const __half2 oz = *(const __half2*)&o4.z, ow = *(const __half2*)&o4.w;
        const __half2 lx = *(const __half2*)&l4.x, ly = *(const __half2*)&l4.y;
        const __half2 lz = *(const __half2*)&l4.z, lw = *(const __half2*)&l4.w;

        // relu(m + (ok-oj)*(lj-lk)), both batches at once.
        a0 = __hadd2(a0, __hfma2_relu(__hsub2(ox, oj2), __hsub2(lj2, lx), m2));
        a1 = __hadd2(a1, __hfma2_relu(__hsub2(oy, oj2), __hsub2(lj2, ly), m2));
        a2 = __hadd2(a2, __hfma2_relu(__hsub2(oz, oj2), __hsub2(lj2, lz), m2));
        a3 = __hadd2(a3, __hfma2_relu(__hsub2(ow, oj2), __hsub2(lj2, lw), m2));
    }

    float2 f0 = __half22float2(a0);
    float2 f1 = __half22float2(a1);
    float2 f2 = __half22float2(a2);
    float2 f3 = __half22float2(a3);
    float acc = (((f0.x + f0.y) + (f1.x + f1.y))
               + ((f2.x + f2.y) + (f3.x + f3.y))) * w;

    // Warp reduce.
    #pragma unroll
    for (int off = 16; off > 0; off >>= 1)
        acc += __shfl_xor_sync(0xFFFFFFFFu, acc, off);
    if (lane == 0) warp_sums[wid] = acc;
    __syncthreads();

    // Single atomic round into d_out (block 0's zero-store happened ~5us ago;
    // within block 0 it is program-ordered before this add).
    if (t == 0) {
        float s = 0.f;
        #pragma unroll
        for (int wdx = 0; wdx < THREADS / 32; wdx++) s += warp_sums[wdx];
        atomicAdd(result, s * (1.0f / (2.0f * PN)));
    }
}

extern "C" void kernel_launch(void* const* d_in, const int* in_sizes, int n_in,
                              void* d_out, int out_size)
{
    const float* g_out    = (const float*)d_in[0];
    const float* g_label  = (const float*)d_in[1];
    const float* g_margin = (const float*)d_in[2];
    float*       result   = (float*)d_out;

    hinge_tile_kernel<<<NBLK, THREADS>>>(g_out, g_label, g_margin, result);
}

// round 17
// speedup vs baseline: 1.2548x; 1.0154x over previous
#include <cuda_runtime.h>
#include <cuda_fp16.h>
#include <cuda_bf16.h>
#include <cstdint>

// Pairwise max-margin hinge loss — SINGLE graph node, no memset.
// 1056 blocks = 528 unordered 32x32 tile-pairs x 2 batch-halves; 256 thr.
// fp16 batch-pair packing (half2 lanes = 2 batches); inner loop uses
// inline-asm ld.shared.v4.b32 so each K fetch is exactly one LDS.128 with
// results used directly as half2 (no vector-member extraction MOVs).
// d_out zeroing: block 0 stores 0 first; atomicAdds land ~5us later.
// loss = [2*offdiag + diag] / (N*2).
// Inputs: out [N,B] f32, label [N,B] f32, margin [1] f32.  N=1024, B=32.

#define PN 1024
#define PB 32
#define NBLK (528 * 2)
#define THREADS 256
#define BH 16              // batches per block (8 pairs)
#define JS2 33             // J stride in half2 units
#define KS2 36             // K stride in half2 units (144B rows, 16B-aligned)

__device__ __forceinline__ unsigned int smem_u32(const void* p) {
    unsigned int a;
    asm("{ .reg .u64 t; cvta.to.shared.u64 t, %1; cvt.u32.u64 %0, t; }"
        : "=r"(a) : "l"(p));
    return a;
}
__device__ __forceinline__ __half2 h2(unsigned int r) {
    __half2 v; *(unsigned int*)&v = r; return v;
}

__global__ __launch_bounds__(THREADS, 8)
void hinge_tile_kernel(const float* __restrict__ g_out,
                       const float* __restrict__ g_label,
                       const float* __restrict__ g_margin,
                       float* __restrict__ result)
{
    // Zero the output first thing, from the first-scheduled block.
    if (blockIdx.x == 0 && threadIdx.x == 0) {
        *result = 0.0f;
    }

    __shared__ __half s_oJ[(BH / 2) * JS2 * 2];
    __shared__ __half s_lJ[(BH / 2) * JS2 * 2];
    __shared__ alignas(16) __half s_oK[(BH / 2) * KS2 * 2];
    __shared__ alignas(16) __half s_lK[(BH / 2) * KS2 * 2];
    __shared__ float warp_sums[THREADS / 32];

    const int p = blockIdx.x >> 1;      // 0..527: unordered tile pair
    const int h = blockIdx.x & 1;       // batch half

    int jt, kt;
    float w;
    if (p < 480)      { int dt = (p >> 5) + 1; jt = p & 31; kt = (jt + dt) & 31; w = 2.0f; }
    else if (p < 496) { jt = p - 480; kt = jt + 16; w = 2.0f; }
    else              { jt = p - 496; kt = jt;      w = 1.0f; }

    const int t    = threadIdx.x;
    const int wid  = t >> 5;
    const int lane = t & 31;

    // Stage with float4 LDG: threads 0-127 -> J tile, 128-255 -> K tile.
    {
        const int i  = t & 127;
        const int n  = i >> 2;          // tile row 0..31
        const int bl = (i & 3) * 4;     // first of 4 consecutive batches
        const int go = n * PB + bl;
        const int bp = bl >> 1;

        if (t < 128) {
            const float4 o4 = *(const float4*)(g_out   + jt * 1024 + h * BH + go);
            const float4 l4 = *(const float4*)(g_label + jt * 1024 + h * BH + go);
            __half2* dsto = (__half2*)s_oJ;
            __half2* dstl = (__half2*)s_lJ;
            dsto[(bp + 0) * JS2 + n] = __floats2half2_rn(o4.x, o4.y);
            dsto[(bp + 1) * JS2 + n] = __floats2half2_rn(o4.z, o4.w);
            dstl[(bp + 0) * JS2 + n] = __floats2half2_rn(l4.x, l4.y);
            dstl[(bp + 1) * JS2 + n] = __floats2half2_rn(l4.z, l4.w);
        } else {
            const float4 o4 = *(const float4*)(g_out   + kt * 1024 + h * BH + go);
            const float4 l4 = *(const float4*)(g_label + kt * 1024 + h * BH + go);
            __half2* dsto = (__half2*)s_oK;
            __half2* dstl = (__half2*)s_lK;
            dsto[(bp + 0) * KS2 + n] = __floats2half2_rn(o4.x, o4.y);
            dsto[(bp + 1) * KS2 + n] = __floats2half2_rn(o4.z, o4.w);
            dstl[(bp + 0) * KS2 + n] = __floats2half2_rn(l4.x, l4.y);
            dstl[(bp + 1) * KS2 + n] = __floats2half2_rn(l4.z, l4.w);
        }
    }
    __syncthreads();

    const __half2 m2 = __float2half2_rn(g_margin[0]);

    // Warp wid owns batch-pair wid; lane = j row in the J tile.
    const __half2 oj2 = ((const __half2*)s_oJ)[wid * JS2 + lane];
    const __half2 lj2 = ((const __half2*)s_lJ)[wid * JS2 + lane];

    const unsigned int koa = smem_u32(s_oK) + (unsigned int)(wid * KS2 * 4);
    const unsigned int kla = smem_u32(s_lK) + (unsigned int)(wid * KS2 * 4);

    __half2 a0 = __float2half2_rn(0.f), a1 = a0, a2 = a0, a3 = a0;

    #pragma unroll
    for (int g = 0; g < 8; g++) {       // 4 k per group, 32 k total
        unsigned int ko0, ko1, ko2, ko3;
        unsigned int kl0, kl1, kl2, kl3;
        // One LDS.128 per array per group; warp-uniform broadcast address.
        asm("ld.shared.v4.b32 {%0,%1,%2,%3}, [%4];"
            : "=r"(ko0), "=r"(ko1), "=r"(ko2), "=r"(ko3)
            : "r"(koa + (unsigned int)(g * 16)));
        asm("ld.shared.v4.b32 {%0,%1,%2,%3}, [%4];"
            : "=r"(kl0), "=r"(kl1), "=r"(kl2), "=r"(kl3)
            : "r"(kla + (unsigned int)(g * 16)));

        // relu(m + (ok-oj)*(lj-lk)), both batches at once.
        a0 = __hadd2(a0, __hfma2_relu(__hsub2(h2(ko0), oj2), __hsub2(lj2, h2(kl0)), m2));
        a1 = __hadd2(a1, __hfma2_relu(__hsub2(h2(ko1), oj2), __hsub2(lj2, h2(kl1)), m2));
        a2 = __hadd2(a2, __hfma2_relu(__hsub2(h2(ko2), oj2), __hsub2(lj2, h2(kl2)), m2));
        a3 = __hadd2(a3, __hfma2_relu(__hsub2(h2(ko3), oj2), __hsub2(lj2, h2(kl3)), m2));
    }

    float2 f0 = __half22float2(a0);
    float2 f1 = __half22float2(a1);
    float2 f2 = __half22float2(a2);
    float2 f3 = __half22float2(a3);
    float acc = (((f0.x + f0.y) + (f1.x + f1.y))
               + ((f2.x + f2.y) + (f3.x + f3.y))) * w;

    // Warp reduce.
    #pragma unroll
    for (int off = 16; off > 0; off >>= 1)
        acc += __shfl_xor_sync(0xFFFFFFFFu, acc, off);
    if (lane == 0) warp_sums[wid] = acc;
    __syncthreads();

    // Single atomic round into d_out.
    if (t == 0) {
        float s = 0.f;
        #pragma unroll
        for (int wdx = 0; wdx < THREADS / 32; wdx++) s += warp_sums[wdx];
        atomicAdd(result, s * (1.0f / (2.0f * PN)));
    }
}

extern "C" void kernel_launch(void* const* d_in, const int* in_sizes, int n_in,
                              void* d_out, int out_size)
{
    const float* g_out    = (const float*)d_in[0];
    const float* g_label  = (const float*)d_in[1];
    const float* g_margin = (const float*)d_in[2];
    float*       result   = (float*)d_out;

    hinge_tile_kernel<<<NBLK, THREADS>>>(g_out, g_label, g_margin, result);
}